// round 2
// baseline (speedup 1.0000x reference)
#include <cuda_runtime.h>
#include <math.h>

#define BB 2048
#define DD 1024
#define RR 64
#define HH 256

// output layout: [out (B*1024)] [W1n (B*64*256)] [W2n (B*256*64)] [ssl_loss (B)]
#define OFF_OUT  0ull
#define OFF_W1   (2048ull*1024ull)
#define OFF_W2   (OFF_W1 + 2048ull*16384ull)
#define OFF_LOSS (OFF_W2 + 2048ull*16384ull)

__device__ float g_K[BB*RR];
__device__ float g_V[BB*RR];
__device__ float g_Q[BB*RR];
__device__ float g_Z[BB*RR];
__device__ float g_eta[BB];

static __device__ __forceinline__ float wredsum(float v) {
#pragma unroll
    for (int o = 16; o; o >>= 1) v += __shfl_xor_sync(0xffffffffu, v, o);
    return v;
}

// tanh-approx GELU (JAX default approximate=True) + analytic derivative
static __device__ __forceinline__ void gelu_fd(float x, float* y, float* dy) {
    const float c = 0.7978845608028654f;
    const float a = 0.044715f;
    float x2 = x * x;
    float u = c * (x + a * x * x2);
    float t = tanhf(u);
    float half1pt = 0.5f * (1.f + t);
    *y  = x * half1pt;
    *dy = half1pt + 0.5f * x * (1.f - t * t) * c * (1.f + 3.f * a * x2);
}

// ---------------------------------------------------------------------------
// proj: C[B,64] = x[B,1024] @ W[1024,64] + bias, for W in {Wk, Wv, Wq}
// tile 64M x 32N, K-tile 32, 256 threads, micro 4x2
// grid: (64, 3)   blockIdx.x: [mtile(32) x ntile(2)], blockIdx.y: matrix
// ---------------------------------------------------------------------------
__global__ void __launch_bounds__(256) proj_kernel(
    const float* __restrict__ x,
    const float* __restrict__ Wk, const float* __restrict__ bk,
    const float* __restrict__ Wv, const float* __restrict__ bv,
    const float* __restrict__ Wq, const float* __restrict__ bq)
{
    const int mat = blockIdx.y;
    const float* W    = (mat == 0) ? Wk : (mat == 1) ? Wv : Wq;
    const float* bias = (mat == 0) ? bk : (mat == 1) ? bv : bq;
    float* Cout       = (mat == 0) ? g_K : (mat == 1) ? g_V : g_Q;

    const int ntile = blockIdx.x & 1;
    const int mtile = blockIdx.x >> 1;
    const int m0 = mtile * 64, n0 = ntile * 32;

    __shared__ float As[32][68];   // As[k][m], padded
    __shared__ float Bs[32][32];

    const int tid = threadIdx.x;
    const int tx = tid & 15;       // n = tx*2
    const int ty = tid >> 4;       // m = ty*4

    float acc[4][2] = {};

    for (int kt = 0; kt < DD; kt += 32) {
#pragma unroll
        for (int l = 0; l < 2; l++) {
            int li  = tid + l * 256;
            int row = li >> 3;
            int c4  = li & 7;
            float4 a = *(const float4*)(x + (size_t)(m0 + row) * DD + kt + c4 * 4);
            As[c4 * 4 + 0][row] = a.x;
            As[c4 * 4 + 1][row] = a.y;
            As[c4 * 4 + 2][row] = a.z;
            As[c4 * 4 + 3][row] = a.w;
        }
        {
            int row = tid >> 3;
            int c4  = tid & 7;
            float4 bv4 = *(const float4*)(W + (size_t)(kt + row) * RR + n0 + c4 * 4);
            *(float4*)(&Bs[row][c4 * 4]) = bv4;
        }
        __syncthreads();
#pragma unroll
        for (int k = 0; k < 32; k++) {
            float a0 = As[k][ty * 4 + 0], a1 = As[k][ty * 4 + 1];
            float a2 = As[k][ty * 4 + 2], a3 = As[k][ty * 4 + 3];
            float b0 = Bs[k][tx * 2 + 0], b1 = Bs[k][tx * 2 + 1];
            acc[0][0] = fmaf(a0, b0, acc[0][0]); acc[0][1] = fmaf(a0, b1, acc[0][1]);
            acc[1][0] = fmaf(a1, b0, acc[1][0]); acc[1][1] = fmaf(a1, b1, acc[1][1]);
            acc[2][0] = fmaf(a2, b0, acc[2][0]); acc[2][1] = fmaf(a2, b1, acc[2][1]);
            acc[3][0] = fmaf(a3, b0, acc[3][0]); acc[3][1] = fmaf(a3, b1, acc[3][1]);
        }
        __syncthreads();
    }
#pragma unroll
    for (int i = 0; i < 4; i++) {
        int row = m0 + ty * 4 + i;
        int col = n0 + tx * 2;
        float2 o;
        o.x = acc[i][0] + bias[col];
        o.y = acc[i][1] + bias[col + 1];
        *(float2*)(Cout + (size_t)row * RR + col) = o;
    }
}

// ---------------------------------------------------------------------------
// eta[b] = 0.1 * sigmoid(x[b]·lr_w + lr_b); one warp per row
// ---------------------------------------------------------------------------
__global__ void __launch_bounds__(256) eta_kernel(
    const float* __restrict__ x, const float* __restrict__ lr_w,
    const float* __restrict__ lr_b)
{
    int warp = threadIdx.x >> 5, lane = threadIdx.x & 31;
    int row = blockIdx.x * 8 + warp;
    const float* xr = x + (size_t)row * DD;
    float s = 0.f;
#pragma unroll 8
    for (int j = lane; j < DD; j += 32) s = fmaf(xr[j], lr_w[j], s);
    s = wredsum(s);
    if (lane == 0) g_eta[row] = 0.1f / (1.f + expf(-(s + lr_b[0])));
}

// ---------------------------------------------------------------------------
// fused per-sample TTT kernel: TWO samples per block (512 threads).
// Halves (tid<256 / tid>=256) share the W1/W2 smem tiles; scratch is per-half.
// Shared tile reads hit identical addresses across halves -> smem broadcast.
// ---------------------------------------------------------------------------
#define SCRATCH_FLOATS 1864
#define SMEM_FLOATS (16384 + 16640 + 128 + 2 * SCRATCH_FLOATS)
#define SMEM_BYTES  (SMEM_FLOATS * 4)

__global__ void __launch_bounds__(512, 1) fused_kernel(
    const float* __restrict__ W1, const float* __restrict__ W2,
    const float* __restrict__ ln_g, const float* __restrict__ ln_b,
    float* __restrict__ outp)
{
    extern __shared__ float sm[];
    float* W1s  = sm;                 // [64][256]
    float* W2s  = sm + 16384;         // [256][65] padded
    float* lng  = W2s + 16640;        // 64
    float* lnb2 = lng + 64;           // 64

    const int tid   = threadIdx.x;
    const int half  = tid >> 8;       // 0 or 1
    const int tl    = tid & 255;      // tid within half
    const int b     = blockIdx.x * 2 + half;

    float* scr  = lnb2 + 64 + half * SCRATCH_FLOATS;
    float* kx    = scr;               // 64
    float* vx    = kx + 64;           // 64
    float* qx    = vx + 64;           // 64
    float* hpre  = qx + 64;           // 256
    float* hv    = hpre + 256;        // 256
    float* dhp   = hv + 256;          // 256
    float* h2    = dhp + 256;         // 256
    float* orr   = h2 + 256;          // 64
    float* dor   = orr + 64;          // 64
    float* opart = dor + 64;          // 256
    float* red   = opart + 256;       // 256
    float* scal  = red + 256;         // 8: [0]=eta [1]=qk [2]=hh2

    // ---- stage loads (whole block cooperates on shared tiles) ----
    for (int i = tid * 4; i < 16384; i += 2048)
        *(float4*)(W1s + i) = *(const float4*)(W1 + i);
    for (int i4 = tid; i4 < 4096; i4 += 512) {
        int idx = i4 * 4;
        int ii = idx >> 6, rr2 = idx & 63;
        float4 w = *(const float4*)(W2 + idx);
        float* dst = W2s + ii * 65 + rr2;
        dst[0] = w.x; dst[1] = w.y; dst[2] = w.z; dst[3] = w.w;
    }
    if (tl < 64) {
        kx[tl] = g_K[b * 64 + tl];
        vx[tl] = g_V[b * 64 + tl];
        qx[tl] = g_Q[b * 64 + tl];
        if (half == 0) {
            lng[tl]  = ln_g[tl];
            lnb2[tl] = ln_b[tl];
        }
    }
    if (tl == 0) scal[0] = g_eta[b];
    __syncthreads();

    // ---- h_pre = k @ W1, h = gelu(h_pre) ----
    {
        float acc = 0.f;
#pragma unroll 8
        for (int r = 0; r < 64; r++) acc = fmaf(kx[r], W1s[r * 256 + tl], acc);
        hpre[tl] = acc;
        float y, dy;
        gelu_fd(acc, &y, &dy);
        hv[tl] = y;
    }
    __syncthreads();

    // ---- o = h @ W2 (partials over 4 chunks of 64) ----
    {
        int c = tl >> 6, r = tl & 63;
        const float* w = W2s + (c * 64) * 65 + r;
        const float* hh = hv + c * 64;
        float acc = 0.f;
#pragma unroll 8
        for (int i = 0; i < 64; i++) acc = fmaf(hh[i], w[i * 65], acc);
        opart[tl] = acc;
    }
    __syncthreads();
    if (tl < 64)
        orr[tl] = opart[tl] + opart[tl + 64] + opart[tl + 128] + opart[tl + 192];
    __syncthreads();

    // ---- LN fwd + loss + LN bwd + qk (first warp of each half) ----
    if (tl < 32) {
        float o0 = orr[tl], o1 = orr[tl + 32];
        float mu = wredsum(o0 + o1) * (1.f / 64.f);
        float d0 = o0 - mu, d1 = o1 - mu;
        float var = wredsum(d0 * d0 + d1 * d1) * (1.f / 64.f);
        float sf = rsqrtf(var + 1e-6f);
        float n0 = d0 * sf, n1 = d1 * sf;
        float g0 = lng[tl], g1 = lng[tl + 32];
        float pred0 = kx[tl]      + n0 * g0 + lnb2[tl];
        float pred1 = kx[tl + 32] + n1 * g1 + lnb2[tl + 32];
        float e0 = pred0 - vx[tl], e1 = pred1 - vx[tl + 32];
        float loss = wredsum(e0 * e0 + e1 * e1) * (1.f / 64.f);
        float dn0 = e0 * (2.f / 64.f) * g0;
        float dn1 = e1 * (2.f / 64.f) * g1;
        float m1 = wredsum(dn0 + dn1) * (1.f / 64.f);
        float m2 = wredsum(dn0 * n0 + dn1 * n1) * (1.f / 64.f);
        dor[tl]      = sf * (dn0 - m1 - n0 * m2);
        dor[tl + 32] = sf * (dn1 - m1 - n1 * m2);
        float qk = wredsum(qx[tl] * kx[tl] + qx[tl + 32] * kx[tl + 32]);
        if (tl == 0) {
            scal[1] = qk;
            outp[OFF_LOSS + b] = loss;
        }
    }
    __syncthreads();

    // ---- dh_pre = (W2 @ do) * gelu'(h_pre);  h2 = gelu(q@W1 - eta*qk*dh_pre) ----
    {
        const float* w = W2s + tl * 65;
        float acc = 0.f;
#pragma unroll 8
        for (int r = 0; r < 64; r++) acc = fmaf(w[r], dor[r], acc);
        float y, dy;
        gelu_fd(hpre[tl], &y, &dy);
        float dhpi = acc * dy;
        dhp[tl] = dhpi;

        float acc2 = 0.f;
#pragma unroll 8
        for (int r = 0; r < 64; r++) acc2 = fmaf(qx[r], W1s[r * 256 + tl], acc2);
        float h2p = acc2 - scal[0] * scal[1] * dhpi;
        float y2, dy2;
        gelu_fd(h2p, &y2, &dy2);
        h2[tl] = y2;
        red[tl] = y2 * hv[tl];  // partial for h2·h
    }
    __syncthreads();

    // ---- o2 partials = h2 @ W2 ----
    {
        int c = tl >> 6, r = tl & 63;
        const float* w = W2s + (c * 64) * 65 + r;
        const float* hh = h2 + c * 64;
        float acc = 0.f;
#pragma unroll 8
        for (int i = 0; i < 64; i++) acc = fmaf(hh[i], w[i * 65], acc);
        opart[tl] = acc;
    }
    __syncthreads();
    if (tl < 32) {
        float hh = red[tl] + red[tl + 32] + red[tl + 64] + red[tl + 96] +
                   red[tl + 128] + red[tl + 160] + red[tl + 192] + red[tl + 224];
        hh = wredsum(hh);
        if (tl == 0) scal[2] = hh;
    }
    __syncthreads();
    if (tl < 64)
        orr[tl] = opart[tl] + opart[tl + 64] + opart[tl + 128] + opart[tl + 192]
                - scal[0] * scal[2] * dor[tl];
    __syncthreads();

    // ---- z = q + LN(o2) (first warp of each half) ----
    if (tl < 32) {
        float o0 = orr[tl], o1 = orr[tl + 32];
        float mu = wredsum(o0 + o1) * (1.f / 64.f);
        float d0 = o0 - mu, d1 = o1 - mu;
        float var = wredsum(d0 * d0 + d1 * d1) * (1.f / 64.f);
        float sf = rsqrtf(var + 1e-6f);
        g_Z[b * 64 + tl]      = qx[tl]      + (d0 * sf) * lng[tl]      + lnb2[tl];
        g_Z[b * 64 + tl + 32] = qx[tl + 32] + (d1 * sf) * lng[tl + 32] + lnb2[tl + 32];
    }

    // ---- write W1n, W2n (values in scratch already final for this half) ----
    const float eta = scal[0];
    float* W1o = outp + OFF_W1 + (size_t)b * 16384;
    for (int i4 = tl; i4 < 4096; i4 += 256) {
        int idx = i4 * 4;
        int r = idx >> 8, i = idx & 255;
        float sc = eta * kx[r];
        float4 w = *(float4*)(W1s + idx);
        float4 ov;
        ov.x = w.x - sc * dhp[i];
        ov.y = w.y - sc * dhp[i + 1];
        ov.z = w.z - sc * dhp[i + 2];
        ov.w = w.w - sc * dhp[i + 3];
        *(float4*)(W1o + idx) = ov;
    }
    float* W2o = outp + OFF_W2 + (size_t)b * 16384;
    for (int i4 = tl; i4 < 4096; i4 += 256) {
        int idx = i4 * 4;
        int i = idx >> 6, r = idx & 63;
        float sc = eta * hv[i];
        const float* ws = W2s + i * 65 + r;
        float4 ov;
        ov.x = ws[0] - sc * dor[r];
        ov.y = ws[1] - sc * dor[r + 1];
        ov.z = ws[2] - sc * dor[r + 2];
        ov.w = ws[3] - sc * dor[r + 3];
        *(float4*)(W2o + idx) = ov;
    }
}

// ---------------------------------------------------------------------------
// out = Z[2048,64] @ Wo[64,1024] + bo ;  tile 64M x 64N, 256 threads, micro 4x4
// grid (32, 16)
// ---------------------------------------------------------------------------
__global__ void __launch_bounds__(256) outgemm_kernel(
    const float* __restrict__ Wo, const float* __restrict__ bo,
    float* __restrict__ outp)
{
    __shared__ float Zs[64][68];   // [k][m], padded
    __shared__ float Ws[64][64];   // [k][n]

    const int m0 = blockIdx.x * 64;
    const int n0 = blockIdx.y * 64;
    const int tid = threadIdx.x;
    const int tx = tid & 15;   // n = tx*4
    const int ty = tid >> 4;   // m = ty*4

#pragma unroll
    for (int l = 0; l < 4; l++) {
        int li = tid + l * 256;
        int row = li >> 4;
        int c4 = li & 15;
        float4 z = *(const float4*)(g_Z + (size_t)(m0 + row) * RR + c4 * 4);
        Zs[c4 * 4 + 0][row] = z.x;
        Zs[c4 * 4 + 1][row] = z.y;
        Zs[c4 * 4 + 2][row] = z.z;
        Zs[c4 * 4 + 3][row] = z.w;
    }
#pragma unroll
    for (int l = 0; l < 4; l++) {
        int li = tid + l * 256;
        int row = li >> 4;
        int c4 = li & 15;
        *(float4*)(&Ws[row][c4 * 4]) =
            *(const float4*)(Wo + (size_t)row * 1024 + n0 + c4 * 4);
    }
    __syncthreads();

    float acc[4][4] = {};
#pragma unroll
    for (int k = 0; k < 64; k++) {
        float a0 = Zs[k][ty * 4 + 0], a1 = Zs[k][ty * 4 + 1];
        float a2 = Zs[k][ty * 4 + 2], a3 = Zs[k][ty * 4 + 3];
        float b0 = Ws[k][tx * 4 + 0], b1 = Ws[k][tx * 4 + 1];
        float b2 = Ws[k][tx * 4 + 2], b3 = Ws[k][tx * 4 + 3];
        acc[0][0] = fmaf(a0, b0, acc[0][0]); acc[0][1] = fmaf(a0, b1, acc[0][1]);
        acc[0][2] = fmaf(a0, b2, acc[0][2]); acc[0][3] = fmaf(a0, b3, acc[0][3]);
        acc[1][0] = fmaf(a1, b0, acc[1][0]); acc[1][1] = fmaf(a1, b1, acc[1][1]);
        acc[1][2] = fmaf(a1, b2, acc[1][2]); acc[1][3] = fmaf(a1, b3, acc[1][3]);
        acc[2][0] = fmaf(a2, b0, acc[2][0]); acc[2][1] = fmaf(a2, b1, acc[2][1]);
        acc[2][2] = fmaf(a2, b2, acc[2][2]); acc[2][3] = fmaf(a2, b3, acc[2][3]);
        acc[3][0] = fmaf(a3, b0, acc[3][0]); acc[3][1] = fmaf(a3, b1, acc[3][1]);
        acc[3][2] = fmaf(a3, b2, acc[3][2]); acc[3][3] = fmaf(a3, b3, acc[3][3]);
    }

    float4 bb = *(const float4*)(bo + n0 + tx * 4);
#pragma unroll
    for (int i = 0; i < 4; i++) {
        int row = m0 + ty * 4 + i;
        float4 ov;
        ov.x = acc[i][0] + bb.x;
        ov.y = acc[i][1] + bb.y;
        ov.z = acc[i][2] + bb.z;
        ov.w = acc[i][3] + bb.w;
        *(float4*)(outp + OFF_OUT + (size_t)row * 1024 + n0 + tx * 4) = ov;
    }
}

// ---------------------------------------------------------------------------
extern "C" void kernel_launch(void* const* d_in, const int* in_sizes, int n_in,
                              void* d_out, int out_size)
{
    const float* x    = (const float*)d_in[0];
    const float* Wk   = (const float*)d_in[1];
    const float* bk   = (const float*)d_in[2];
    const float* Wv   = (const float*)d_in[3];
    const float* bv   = (const float*)d_in[4];
    const float* Wq   = (const float*)d_in[5];
    const float* bq   = (const float*)d_in[6];
    const float* Wo   = (const float*)d_in[7];
    const float* bo   = (const float*)d_in[8];
    const float* ln_g = (const float*)d_in[9];
    const float* ln_b = (const float*)d_in[10];
    const float* lr_w = (const float*)d_in[11];
    const float* lr_b = (const float*)d_in[12];
    const float* W1   = (const float*)d_in[13];
    const float* W2   = (const float*)d_in[14];
    float* outp = (float*)d_out;

    cudaFuncSetAttribute(fused_kernel,
                         cudaFuncAttributeMaxDynamicSharedMemorySize, SMEM_BYTES);

    proj_kernel<<<dim3(64, 3), 256>>>(x, Wk, bk, Wv, bv, Wq, bq);
    eta_kernel<<<256, 256>>>(x, lr_w, lr_b);
    fused_kernel<<<1024, 512, SMEM_BYTES>>>(W1, W2, ln_g, ln_b, outp);
    outgemm_kernel<<<dim3(32, 16), 256>>>(Wo, bo, outp);
}

// round 4
// speedup vs baseline: 1.2153x; 1.2153x over previous
#include <cuda_runtime.h>
#include <math.h>

#define BB 2048
#define DD 1024
#define RR 64
#define HH 256

// output layout: [out (B*1024)] [W1n (B*64*256)] [W2n (B*256*64)] [ssl_loss (B)]
#define OFF_OUT  0ull
#define OFF_W1   (2048ull*1024ull)
#define OFF_W2   (OFF_W1 + 2048ull*16384ull)
#define OFF_LOSS (OFF_W2 + 2048ull*16384ull)

__device__ float g_K[BB*RR];
__device__ float g_V[BB*RR];
__device__ float g_Q[BB*RR];
__device__ float g_Z[BB*RR];
__device__ float g_eta[BB];
__device__ float g_EK[BB*RR];    // eta * k
__device__ float g_DHP[BB*HH];   // dh_pre
__device__ float g_HVe[BB*HH];   // eta * h
__device__ float g_DOR[BB*RR];   // dL/do

static __device__ __forceinline__ float wredsum(float v) {
#pragma unroll
    for (int o = 16; o; o >>= 1) v += __shfl_xor_sync(0xffffffffu, v, o);
    return v;
}

static __device__ __forceinline__ void gelu_fd(float x, float* y, float* dy) {
    const float c = 0.7978845608028654f;
    const float a = 0.044715f;
    float x2 = x * x;
    float u = c * (x + a * x * x2);
    float t = tanhf(u);
    float half1pt = 0.5f * (1.f + t);
    *y  = x * half1pt;
    *dy = half1pt + 0.5f * x * (1.f - t * t) * c * (1.f + 3.f * a * x2);
}

// ---------------------------------------------------------------------------
// proj: C[B,64] = x[B,1024] @ W[1024,64] + bias, for W in {Wk, Wv, Wq}
// ---------------------------------------------------------------------------
__global__ void __launch_bounds__(256) proj_kernel(
    const float* __restrict__ x,
    const float* __restrict__ Wk, const float* __restrict__ bk,
    const float* __restrict__ Wv, const float* __restrict__ bv,
    const float* __restrict__ Wq, const float* __restrict__ bq)
{
    const int mat = blockIdx.y;
    const float* W    = (mat == 0) ? Wk : (mat == 1) ? Wv : Wq;
    const float* bias = (mat == 0) ? bk : (mat == 1) ? bv : bq;
    float* Cout       = (mat == 0) ? g_K : (mat == 1) ? g_V : g_Q;

    const int ntile = blockIdx.x & 1;
    const int mtile = blockIdx.x >> 1;
    const int m0 = mtile * 64, n0 = ntile * 32;

    __shared__ float As[32][68];
    __shared__ float Bs[32][32];

    const int tid = threadIdx.x;
    const int tx = tid & 15;
    const int ty = tid >> 4;

    float acc[4][2] = {};

    for (int kt = 0; kt < DD; kt += 32) {
#pragma unroll
        for (int l = 0; l < 2; l++) {
            int li  = tid + l * 256;
            int row = li >> 3;
            int c4  = li & 7;
            float4 a = *(const float4*)(x + (size_t)(m0 + row) * DD + kt + c4 * 4);
            As[c4 * 4 + 0][row] = a.x;
            As[c4 * 4 + 1][row] = a.y;
            As[c4 * 4 + 2][row] = a.z;
            As[c4 * 4 + 3][row] = a.w;
        }
        {
            int row = tid >> 3;
            int c4  = tid & 7;
            float4 bv4 = *(const float4*)(W + (size_t)(kt + row) * RR + n0 + c4 * 4);
            *(float4*)(&Bs[row][c4 * 4]) = bv4;
        }
        __syncthreads();
#pragma unroll
        for (int k = 0; k < 32; k++) {
            float a0 = As[k][ty * 4 + 0], a1 = As[k][ty * 4 + 1];
            float a2 = As[k][ty * 4 + 2], a3 = As[k][ty * 4 + 3];
            float b0 = Bs[k][tx * 2 + 0], b1 = Bs[k][tx * 2 + 1];
            acc[0][0] = fmaf(a0, b0, acc[0][0]); acc[0][1] = fmaf(a0, b1, acc[0][1]);
            acc[1][0] = fmaf(a1, b0, acc[1][0]); acc[1][1] = fmaf(a1, b1, acc[1][1]);
            acc[2][0] = fmaf(a2, b0, acc[2][0]); acc[2][1] = fmaf(a2, b1, acc[2][1]);
            acc[3][0] = fmaf(a3, b0, acc[3][0]); acc[3][1] = fmaf(a3, b1, acc[3][1]);
        }
        __syncthreads();
    }
#pragma unroll
    for (int i = 0; i < 4; i++) {
        int row = m0 + ty * 4 + i;
        int col = n0 + tx * 2;
        float2 o;
        o.x = acc[i][0] + bias[col];
        o.y = acc[i][1] + bias[col + 1];
        *(float2*)(Cout + (size_t)row * RR + col) = o;
    }
}

// ---------------------------------------------------------------------------
// eta[b] = 0.1 * sigmoid(x[b]·lr_w + lr_b)
// ---------------------------------------------------------------------------
__global__ void __launch_bounds__(256) eta_kernel(
    const float* __restrict__ x, const float* __restrict__ lr_w,
    const float* __restrict__ lr_b)
{
    int warp = threadIdx.x >> 5, lane = threadIdx.x & 31;
    int row = blockIdx.x * 8 + warp;
    const float* xr = x + (size_t)row * DD;
    float s = 0.f;
#pragma unroll 8
    for (int j = lane; j < DD; j += 32) s = fmaf(xr[j], lr_w[j], s);
    s = wredsum(s);
    if (lane == 0) g_eta[row] = 0.1f / (1.f + expf(-(s + lr_b[0])));
}

// ---------------------------------------------------------------------------
// compute kernel: S=16 samples per block, 256 threads, 128 blocks (1 wave).
// Stages W1/W2 once, runs all per-sample math batched, emits small vectors.
// ---------------------------------------------------------------------------
#define CS 16
#define CSM_FLOATS (16384 + 16640 + 1024*3 + 64 + 64 + 4096*4 + 1024*2 + 128 + 48)
#define CSM_BYTES  (CSM_FLOATS * 4)

__global__ void __launch_bounds__(256, 1) compute_kernel(
    const float* __restrict__ W1, const float* __restrict__ W2,
    const float* __restrict__ ln_g, const float* __restrict__ ln_b,
    float* __restrict__ outp)
{
    extern __shared__ float sm[];
    float* W1s  = sm;                  // [64][256]
    float* W2s  = W1s + 16384;         // [256][65] padded
    float* KX   = W2s + 16640;         // [16][64]
    float* VX   = KX + 1024;           // [16][64]
    float* QX   = VX + 1024;           // [16][64]
    float* LNG  = QX + 1024;           // 64
    float* LNB  = LNG + 64;            // 64
    float* HPRE = LNB + 64;            // [16][256]  (reused as H2)
    float* HV   = HPRE + 4096;         // [16][256]
    float* DHP  = HV + 4096;           // [16][256]
    float* GDY  = DHP + 4096;          // [16][256]
    float* ORR  = GDY + 4096;          // [16][64]
    float* DORs = ORR + 1024;          // [16][64]
    float* RED  = DORs + 1024;         // [16][8]
    float* SC_ETA = RED + 128;         // 16
    float* SC_QK  = SC_ETA + 16;       // 16
    float* SC_HH  = SC_QK + 16;        // 16

    const int tid  = threadIdx.x;
    const int b0   = blockIdx.x * CS;
    const int lane = tid & 31;
    const int wrp  = tid >> 5;

    // ---- P0: stage ----
#pragma unroll
    for (int l = 0; l < 16; l++) {
        int i = (tid + l * 256) * 4;
        *(float4*)(W1s + i) = *(const float4*)(W1 + i);
    }
#pragma unroll
    for (int l = 0; l < 16; l++) {
        int i4 = tid + l * 256;
        int idx = i4 * 4;
        int ii = idx >> 6, rr2 = idx & 63;
        float4 w = *(const float4*)(W2 + idx);
        float* dst = W2s + ii * 65 + rr2;
        dst[0] = w.x; dst[1] = w.y; dst[2] = w.z; dst[3] = w.w;
    }
    *(float4*)(KX + tid * 4) = *(const float4*)(g_K + (size_t)b0 * 64 + tid * 4);
    *(float4*)(VX + tid * 4) = *(const float4*)(g_V + (size_t)b0 * 64 + tid * 4);
    *(float4*)(QX + tid * 4) = *(const float4*)(g_Q + (size_t)b0 * 64 + tid * 4);
    if (tid < 64) { LNG[tid] = ln_g[tid]; LNB[tid] = ln_b[tid]; }
    if (tid < CS) SC_ETA[tid] = g_eta[b0 + tid];
    __syncthreads();

    // write g_EK = eta * k
    for (int idx = tid; idx < CS * 64; idx += 256)
        g_EK[(size_t)b0 * 64 + idx] = SC_ETA[idx >> 6] * KX[idx];

    // ---- P1: hpre = k@W1, hv = gelu, store dy ----
    {
        float acc[CS];
#pragma unroll
        for (int s = 0; s < CS; s++) acc[s] = 0.f;
#pragma unroll 4
        for (int r = 0; r < 64; r++) {
            float w = W1s[r * 256 + tid];
#pragma unroll
            for (int s = 0; s < CS; s++) acc[s] = fmaf(w, KX[s * 64 + r], acc[s]);
        }
#pragma unroll
        for (int s = 0; s < CS; s++) {
            float y, dy;
            gelu_fd(acc[s], &y, &dy);
            HPRE[s * 256 + tid] = acc[s];
            HV[s * 256 + tid]   = y;
            GDY[s * 256 + tid]  = dy;
            g_HVe[(size_t)(b0 + s) * 256 + tid] = SC_ETA[s] * y;
        }
    }
    __syncthreads();

    // ---- P2: o = h@W2 ----
    {
        const int r = tid & 63, sq = tid >> 6;
        float acc[4] = {};
        for (int i = 0; i < 256; i++) {
            float w = W2s[i * 65 + r];
#pragma unroll
            for (int j = 0; j < 4; j++)
                acc[j] = fmaf(w, HV[(sq + 4 * j) * 256 + i], acc[j]);
        }
#pragma unroll
        for (int j = 0; j < 4; j++) ORR[(sq + 4 * j) * 64 + r] = acc[j];
    }
    __syncthreads();

    // ---- P3: LN fwd + loss + LN bwd + qk (warp w -> samples 2w, 2w+1) ----
#pragma unroll
    for (int sl = 0; sl < 2; sl++) {
        int s = wrp * 2 + sl;
        float o0 = ORR[s * 64 + lane], o1 = ORR[s * 64 + lane + 32];
        float mu = wredsum(o0 + o1) * (1.f / 64.f);
        float d0 = o0 - mu, d1 = o1 - mu;
        float var = wredsum(d0 * d0 + d1 * d1) * (1.f / 64.f);
        float sf = rsqrtf(var + 1e-6f);
        float n0 = d0 * sf, n1 = d1 * sf;
        float g0 = LNG[lane], g1 = LNG[lane + 32];
        float k0 = KX[s * 64 + lane], k1 = KX[s * 64 + lane + 32];
        float pred0 = k0 + n0 * g0 + LNB[lane];
        float pred1 = k1 + n1 * g1 + LNB[lane + 32];
        float e0 = pred0 - VX[s * 64 + lane], e1 = pred1 - VX[s * 64 + lane + 32];
        float loss = wredsum(e0 * e0 + e1 * e1) * (1.f / 64.f);
        float dn0 = e0 * (2.f / 64.f) * g0;
        float dn1 = e1 * (2.f / 64.f) * g1;
        float m1 = wredsum(dn0 + dn1) * (1.f / 64.f);
        float m2 = wredsum(dn0 * n0 + dn1 * n1) * (1.f / 64.f);
        float dd0 = sf * (dn0 - m1 - n0 * m2);
        float dd1 = sf * (dn1 - m1 - n1 * m2);
        DORs[s * 64 + lane]      = dd0;
        DORs[s * 64 + lane + 32] = dd1;
        g_DOR[(size_t)(b0 + s) * 64 + lane]      = dd0;
        g_DOR[(size_t)(b0 + s) * 64 + lane + 32] = dd1;
        float qk = wredsum(QX[s * 64 + lane] * k0 + QX[s * 64 + lane + 32] * k1);
        if (lane == 0) {
            SC_QK[s] = qk;
            outp[OFF_LOSS + b0 + s] = loss;
        }
    }
    __syncthreads();

    // ---- P4: dhp = (W2@do)*gelu'(hpre); h2 = gelu(q@W1 - eta*qk*dhp); red ----
    {
        float acc[CS];
#pragma unroll
        for (int s = 0; s < CS; s++) acc[s] = 0.f;
#pragma unroll 4
        for (int r = 0; r < 64; r++) {
            float w = W2s[tid * 65 + r];
#pragma unroll
            for (int s = 0; s < CS; s++) acc[s] = fmaf(w, DORs[s * 64 + r], acc[s]);
        }
        float acc2[CS];
#pragma unroll
        for (int s = 0; s < CS; s++) acc2[s] = 0.f;
#pragma unroll 4
        for (int r = 0; r < 64; r++) {
            float w = W1s[r * 256 + tid];
#pragma unroll
            for (int s = 0; s < CS; s++) acc2[s] = fmaf(w, QX[s * 64 + r], acc2[s]);
        }
        float prod[CS];
#pragma unroll
        for (int s = 0; s < CS; s++) {
            float dhpi = acc[s] * GDY[s * 256 + tid];
            DHP[s * 256 + tid] = dhpi;
            g_DHP[(size_t)(b0 + s) * 256 + tid] = dhpi;
            float h2p = acc2[s] - SC_ETA[s] * SC_QK[s] * dhpi;
            float y2, dy2;
            gelu_fd(h2p, &y2, &dy2);
            HPRE[s * 256 + tid] = y2;          // H2 overwrites HPRE
            prod[s] = y2 * HV[s * 256 + tid];
        }
#pragma unroll
        for (int s = 0; s < CS; s++) {
            float p = wredsum(prod[s]);
            if (lane == 0) RED[s * 8 + wrp] = p;
        }
    }
    __syncthreads();
    if (tid < CS) {
        float hh = 0.f;
#pragma unroll
        for (int w = 0; w < 8; w++) hh += RED[tid * 8 + w];
        SC_HH[tid] = hh;
    }
    __syncthreads();

    // ---- P5: o2 = h2@W2 - eta*hh*do ----
    {
        const int r = tid & 63, sq = tid >> 6;
        float acc[4] = {};
        for (int i = 0; i < 256; i++) {
            float w = W2s[i * 65 + r];
#pragma unroll
            for (int j = 0; j < 4; j++)
                acc[j] = fmaf(w, HPRE[(sq + 4 * j) * 256 + i], acc[j]);
        }
#pragma unroll
        for (int j = 0; j < 4; j++) {
            int s = sq + 4 * j;
            ORR[s * 64 + r] = acc[j] - SC_ETA[s] * SC_HH[s] * DORs[s * 64 + r];
        }
    }
    __syncthreads();

    // ---- P6: z = q + LN(o2) ----
#pragma unroll
    for (int sl = 0; sl < 2; sl++) {
        int s = wrp * 2 + sl;
        float o0 = ORR[s * 64 + lane], o1 = ORR[s * 64 + lane + 32];
        float mu = wredsum(o0 + o1) * (1.f / 64.f);
        float d0 = o0 - mu, d1 = o1 - mu;
        float var = wredsum(d0 * d0 + d1 * d1) * (1.f / 64.f);
        float sf = rsqrtf(var + 1e-6f);
        g_Z[(size_t)(b0 + s) * 64 + lane] =
            QX[s * 64 + lane] + (d0 * sf) * LNG[lane] + LNB[lane];
        g_Z[(size_t)(b0 + s) * 64 + lane + 32] =
            QX[s * 64 + lane + 32] + (d1 * sf) * LNG[lane + 32] + LNB[lane + 32];
    }
}

// ---------------------------------------------------------------------------
// merged epilogue + outgemm kernel. 256 threads.
// blocks [0,512): outgemm tiles; [512,1024): W1n; [1024,1536): W2n
// ---------------------------------------------------------------------------
__global__ void __launch_bounds__(256) epi_out_kernel(
    const float* __restrict__ W1, const float* __restrict__ W2,
    const float* __restrict__ Wo, const float* __restrict__ bo,
    float* __restrict__ outp)
{
    __shared__ float SBUF[8448];
    const int bid = blockIdx.x;
    const int tid = threadIdx.x;

    if (bid < 512) {
        // ---- outgemm: out = Z @ Wo + bo ----
        float (*Zs)[68] = (float(*)[68])SBUF;            // [64][68]
        float (*Ws)[64] = (float(*)[64])(SBUF + 4352);   // [64][64]
        const int m0 = (bid & 31) * 64;
        const int n0 = (bid >> 5) * 64;
        const int tx = tid & 15;
        const int ty = tid >> 4;

#pragma unroll
        for (int l = 0; l < 4; l++) {
            int li = tid + l * 256;
            int row = li >> 4;
            int c4 = li & 15;
            float4 z = *(const float4*)(g_Z + (size_t)(m0 + row) * RR + c4 * 4);
            Zs[c4 * 4 + 0][row] = z.x;
            Zs[c4 * 4 + 1][row] = z.y;
            Zs[c4 * 4 + 2][row] = z.z;
            Zs[c4 * 4 + 3][row] = z.w;
        }
#pragma unroll
        for (int l = 0; l < 4; l++) {
            int li = tid + l * 256;
            int row = li >> 4;
            int c4 = li & 15;
            *(float4*)(&Ws[row][c4 * 4]) =
                *(const float4*)(Wo + (size_t)row * 1024 + n0 + c4 * 4);
        }
        __syncthreads();

        float acc[4][4] = {};
#pragma unroll
        for (int k = 0; k < 64; k++) {
            float a0 = Zs[k][ty * 4 + 0], a1 = Zs[k][ty * 4 + 1];
            float a2 = Zs[k][ty * 4 + 2], a3 = Zs[k][ty * 4 + 3];
            float b0 = Ws[k][tx * 4 + 0], b1 = Ws[k][tx * 4 + 1];
            float b2 = Ws[k][tx * 4 + 2], b3 = Ws[k][tx * 4 + 3];
            acc[0][0] = fmaf(a0, b0, acc[0][0]); acc[0][1] = fmaf(a0, b1, acc[0][1]);
            acc[0][2] = fmaf(a0, b2, acc[0][2]); acc[0][3] = fmaf(a0, b3, acc[0][3]);
            acc[1][0] = fmaf(a1, b0, acc[1][0]); acc[1][1] = fmaf(a1, b1, acc[1][1]);
            acc[1][2] = fmaf(a1, b2, acc[1][2]); acc[1][3] = fmaf(a1, b3, acc[1][3]);
            acc[2][0] = fmaf(a2, b0, acc[2][0]); acc[2][1] = fmaf(a2, b1, acc[2][1]);
            acc[2][2] = fmaf(a2, b2, acc[2][2]); acc[2][3] = fmaf(a2, b3, acc[2][3]);
            acc[3][0] = fmaf(a3, b0, acc[3][0]); acc[3][1] = fmaf(a3, b1, acc[3][1]);
            acc[3][2] = fmaf(a3, b2, acc[3][2]); acc[3][3] = fmaf(a3, b3, acc[3][3]);
        }

        float4 bb = *(const float4*)(bo + n0 + tx * 4);
#pragma unroll
        for (int i = 0; i < 4; i++) {
            int row = m0 + ty * 4 + i;
            float4 ov;
            ov.x = acc[i][0] + bb.x;
            ov.y = acc[i][1] + bb.y;
            ov.z = acc[i][2] + bb.z;
            ov.w = acc[i][3] + bb.w;
            *(float4*)(outp + OFF_OUT + (size_t)row * 1024 + n0 + tx * 4) = ov;
        }
    } else if (bid < 1024) {
        // ---- W1n epilogue: 16 samples x 16 W1-rows per block ----
        const int e = bid - 512;
        const int g0 = (e >> 2) * 16;      // sample group base
        const int r0 = (e & 3) * 16;       // row slice base
        float* W1sl = SBUF;                // [16*256] flat
        float* EKs  = SBUF + 4096;         // [16][16]
        float* DHPs = SBUF + 4352;         // [16][256] flat

#pragma unroll
        for (int l = 0; l < 4; l++) {
            int i4 = tid + l * 256;
            *(float4*)(W1sl + i4 * 4) = *(const float4*)(W1 + (size_t)r0 * 256 + i4 * 4);
        }
        EKs[tid] = g_EK[(size_t)(g0 + (tid >> 4)) * 64 + r0 + (tid & 15)];
#pragma unroll
        for (int l = 0; l < 4; l++) {
            int i4 = tid + l * 256;
            *(float4*)(DHPs + i4 * 4) = *(const float4*)(g_DHP + (size_t)g0 * 256 + i4 * 4);
        }
        __syncthreads();

        // 2 independent stores per iteration for store-stream MLP
        for (int idx = tid; idx < 16384; idx += 512) {
#pragma unroll
            for (int u = 0; u < 2; u++) {
                int id2 = idx + u * 256;
                int s = id2 >> 10;
                int rem = id2 & 1023;
                int r = rem >> 6, i4 = rem & 63;
                float sc = EKs[s * 16 + r];
                float4 w = *(float4*)(W1sl + rem * 4);
                float4 d = *(float4*)(DHPs + s * 256 + i4 * 4);
                float4 ov;
                ov.x = w.x - sc * d.x;
                ov.y = w.y - sc * d.y;
                ov.z = w.z - sc * d.z;
                ov.w = w.w - sc * d.w;
                *(float4*)(outp + OFF_W1 + (size_t)(g0 + s) * 16384 +
                           (size_t)r0 * 256 + rem * 4) = ov;
            }
        }
    } else {
        // ---- W2n epilogue: 16 samples x 64 W2-i-rows per block ----
        const int e = bid - 1024;
        const int g0 = (e >> 2) * 16;
        const int i0 = (e & 3) * 64;
        float* W2sl  = SBUF;               // [64*64] flat
        float* HVes  = SBUF + 4096;        // [16][64]
        float* DORs2 = SBUF + 5120;        // [16][64]

#pragma unroll
        for (int l = 0; l < 4; l++) {
            int i4 = tid + l * 256;
            *(float4*)(W2sl + i4 * 4) = *(const float4*)(W2 + (size_t)i0 * 64 + i4 * 4);
        }
        {
            int s = tid >> 4, ii4 = tid & 15;
            *(float4*)(HVes + s * 64 + ii4 * 4) =
                *(const float4*)(g_HVe + (size_t)(g0 + s) * 256 + i0 + ii4 * 4);
        }
        *(float4*)(DORs2 + tid * 4) = *(const float4*)(g_DOR + (size_t)g0 * 64 + tid * 4);
        __syncthreads();

        for (int idx = tid; idx < 16384; idx += 512) {
#pragma unroll
            for (int u = 0; u < 2; u++) {
                int id2 = idx + u * 256;
                int s = id2 >> 10;
                int rem = id2 & 1023;
                int i = rem >> 4, r4 = rem & 15;
                float sc = HVes[s * 64 + i];
                float4 w = *(float4*)(W2sl + rem * 4);
                float4 d = *(float4*)(DORs2 + s * 64 + r4 * 4);
                float4 ov;
                ov.x = w.x - sc * d.x;
                ov.y = w.y - sc * d.y;
                ov.z = w.z - sc * d.z;
                ov.w = w.w - sc * d.w;
                *(float4*)(outp + OFF_W2 + (size_t)(g0 + s) * 16384 +
                           (size_t)i0 * 64 + rem * 4) = ov;
            }
        }
    }
}

// ---------------------------------------------------------------------------
extern "C" void kernel_launch(void* const* d_in, const int* in_sizes, int n_in,
                              void* d_out, int out_size)
{
    const float* x    = (const float*)d_in[0];
    const float* Wk   = (const float*)d_in[1];
    const float* bk   = (const float*)d_in[2];
    const float* Wv   = (const float*)d_in[3];
    const float* bv   = (const float*)d_in[4];
    const float* Wq   = (const float*)d_in[5];
    const float* bq   = (const float*)d_in[6];
    const float* Wo   = (const float*)d_in[7];
    const float* bo   = (const float*)d_in[8];
    const float* ln_g = (const float*)d_in[9];
    const float* ln_b = (const float*)d_in[10];
    const float* lr_w = (const float*)d_in[11];
    const float* lr_b = (const float*)d_in[12];
    const float* W1   = (const float*)d_in[13];
    const float* W2   = (const float*)d_in[14];
    float* outp = (float*)d_out;

    cudaFuncSetAttribute(compute_kernel,
                         cudaFuncAttributeMaxDynamicSharedMemorySize, CSM_BYTES);

    proj_kernel<<<dim3(64, 3), 256>>>(x, Wk, bk, Wv, bv, Wq, bq);
    eta_kernel<<<256, 256>>>(x, lr_w, lr_b);
    compute_kernel<<<128, 256, CSM_BYTES>>>(W1, W2, ln_g, ln_b, outp);
    epi_out_kernel<<<1536, 256>>>(W1, W2, Wo, bo, outp);
}